// round 1
// baseline (speedup 1.0000x reference)
#include <cuda_runtime.h>
#include <math.h>

// Problem constants (validated against in_sizes at runtime via division)
#define NN 50000
#define EE 800000

// ---------------- scratch (static device globals; no allocations) ----------------
__device__ float g_dinv[NN];
__device__ int   g_deg[NN];
__device__ float g_norm[EE];
__device__ float g_h   [(size_t)NN * 64];       // inter-layer activations
__device__ float g_buf0[(size_t)2 * NN * 64];   // out0 (pre-propagate)
__device__ float g_agg [(size_t)2 * NN * 64];   // scatter destination
__device__ float g_buf2[(size_t)2 * NN * 64];   // t0 output / final per-k
__device__ float g_buf3[(size_t)2 * NN * 64];   // out_t0 @ W
__device__ float g_buf4[(size_t)2 * NN * 64];   // dense1

// ---------------- small utility kernels ----------------
__global__ void k_zero4(float4* p, int n4) {
    int i = blockIdx.x * blockDim.x + threadIdx.x;
    if (i < n4) p[i] = make_float4(0.f, 0.f, 0.f, 0.f);
}

__global__ void k_zero_int(int* p, int n) {
    int i = blockIdx.x * blockDim.x + threadIdx.x;
    if (i < n) p[i] = 0;
}

__global__ void k_deg(const int* __restrict__ col, int* __restrict__ deg, int E) {
    int e = blockIdx.x * blockDim.x + threadIdx.x;
    if (e < E) atomicAdd(&deg[col[e]], 1);
}

__global__ void k_dinv(const int* __restrict__ deg, float* __restrict__ dinv, int n) {
    int i = blockIdx.x * blockDim.x + threadIdx.x;
    if (i < n) {
        int d = deg[i];
        dinv[i] = (d > 0) ? rsqrtf((float)d) : 0.f;
    }
}

__global__ void k_norm(const int* __restrict__ row, const int* __restrict__ col,
                       const float* __restrict__ dinv, float* __restrict__ nrm, int E) {
    int e = blockIdx.x * blockDim.x + threadIdx.x;
    if (e < E) nrm[e] = dinv[row[e]] * dinv[col[e]];
}

// ---------------- message passing: gather * norm -> atomic scatter-add ----------------
// thread = (edge, chunk) where chunk spans K * F/4 float4s; consecutive threads
// share an edge -> coalesced gather of the source row, coalesced atomics on target row.
__global__ void k_scatter(const float* __restrict__ src, float* __restrict__ dst,
                          const int* __restrict__ row, const int* __restrict__ col,
                          const float* __restrict__ nrm,
                          int E, int F4, int chunks, long sK) {
    int idx = blockIdx.x * blockDim.x + threadIdx.x;
    if (idx >= E * chunks) return;
    int e  = idx / chunks;
    int c  = idx - e * chunks;
    int k  = c / F4;
    int cc = c - k * F4;
    int r = row[e], t = col[e];
    float nv = nrm[e];
    const float4 v = *(const float4*)(src + (long)k * sK + ((long)r * F4 + cc) * 4);
    float* d = dst + (long)k * sK + ((long)t * F4 + cc) * 4;
    atomicAdd(d + 0, v.x * nv);
    atomicAdd(d + 1, v.y * nv);
    atomicAdd(d + 2, v.z * nv);
    atomicAdd(d + 3, v.w * nv);
}

// ---------------- fused SGEMM ----------------
// C[k] = act( A[k] @ B[k] + D1[k] + alpha2*D2[k] + bias_scalar )
// A is [nRows, Fin] row-major; B is [Fin, FO]; optional A2: A-load becomes 0.5*(A+A2) (mean over K=2).
// Tile: 128 rows x FO cols per block; micro-tile 4x8 per thread; B fully SMEM-resident.
template<int FO>
__global__ __launch_bounds__(32 * (FO / 8))
void k_gemm(const float* __restrict__ A, const float* __restrict__ A2, long aK,
            const float* __restrict__ B, long bK,
            const float* __restrict__ D1, long dK,
            const float* __restrict__ D2, float alpha2,
            const float* __restrict__ biasPtr,
            float* __restrict__ C, long cK,
            int nRows, int Fin, int act) {
    constexpr int TX = FO / 8;
    const int k = blockIdx.z;
    A += (long)k * aK;
    B += (long)k * bK;
    C += (long)k * cK;
    const float* d1 = D1 ? (D1 + (long)k * dK) : nullptr;
    const float* d2 = D2 ? (D2 + (long)k * dK) : nullptr;
    const float* a2 = A2 ? (A2 + (long)k * aK) : nullptr;

    __shared__ float Bs[128][FO];   // whole B (Fin <= 128)
    __shared__ float As[128][17];   // 16-wide K chunk, padded

    const int tid = threadIdx.x;
    const int nthreads = 32 * TX;
    const int tx = tid % TX;        // 8 output cols each
    const int ty = tid / TX;        // 0..31, 4 rows each
    const int row0 = blockIdx.x * 128;

    for (int i = tid; i < Fin * FO; i += nthreads)
        ((float*)Bs)[i] = B[i];

    float acc[4][8];
#pragma unroll
    for (int i = 0; i < 4; i++)
#pragma unroll
        for (int j = 0; j < 8; j++) acc[i][j] = 0.f;

    for (int kk0 = 0; kk0 < Fin; kk0 += 16) {
        __syncthreads();            // covers B load on first iter, As reuse after
        for (int i = tid; i < 128 * 16; i += nthreads) {
            int r = i >> 4, c = i & 15;
            int gr = row0 + r;
            float v = 0.f;
            if (gr < nRows) {
                v = A[(long)gr * Fin + kk0 + c];
                if (a2) v = 0.5f * (v + a2[(long)gr * Fin + kk0 + c]);
            }
            As[r][c] = v;
        }
        __syncthreads();
#pragma unroll
        for (int kk = 0; kk < 16; kk++) {
            float4 bA = *(const float4*)&Bs[kk0 + kk][tx * 8];
            float4 bB = *(const float4*)&Bs[kk0 + kk][tx * 8 + 4];
#pragma unroll
            for (int i = 0; i < 4; i++) {
                float a = As[ty * 4 + i][kk];
                acc[i][0] += a * bA.x; acc[i][1] += a * bA.y;
                acc[i][2] += a * bA.z; acc[i][3] += a * bA.w;
                acc[i][4] += a * bB.x; acc[i][5] += a * bB.y;
                acc[i][6] += a * bB.z; acc[i][7] += a * bB.w;
            }
        }
    }

    float bv = biasPtr ? __ldg(biasPtr) : 0.f;
#pragma unroll
    for (int i = 0; i < 4; i++) {
        int gr = row0 + ty * 4 + i;
        if (gr < nRows) {
            long base = (long)gr * FO + tx * 8;
#pragma unroll
            for (int j = 0; j < 8; j++) {
                float v = acc[i][j];
                if (d1) v += d1[base + j];
                if (d2) v += alpha2 * d2[base + j];
                v += bv;
                if (act) v = (v >= 0.f) ? v : 0.2f * v;
                C[base + j] = v;
            }
        }
    }
}

// y = relu(a + b) : sum over K=2 stacks + inter-layer ReLU
__global__ void k_combine(const float4* __restrict__ a, const float4* __restrict__ b,
                          float4* __restrict__ o, int n4) {
    int i = blockIdx.x * blockDim.x + threadIdx.x;
    if (i < n4) {
        float4 x = a[i], y = b[i];
        float4 r;
        r.x = fmaxf(x.x + y.x, 0.f);
        r.y = fmaxf(x.y + y.y, 0.f);
        r.z = fmaxf(x.z + y.z, 0.f);
        r.w = fmaxf(x.w + y.w, 0.f);
        o[i] = r;
    }
}

// warp-per-row log_softmax, C == 32 lanes
__global__ void k_logsoftmax(const float* __restrict__ in, float* __restrict__ out, int n) {
    int warp = (blockIdx.x * blockDim.x + threadIdx.x) >> 5;
    int lane = threadIdx.x & 31;
    if (warp >= n) return;
    float v = in[(long)warp * 32 + lane];
    float m = v;
#pragma unroll
    for (int o = 16; o > 0; o >>= 1) m = fmaxf(m, __shfl_xor_sync(0xffffffffu, m, o));
    float e = expf(v - m);
    float s = e;
#pragma unroll
    for (int o = 16; o > 0; o >>= 1) s += __shfl_xor_sync(0xffffffffu, s, o);
    out[(long)warp * 32 + lane] = v - m - logf(s);
}

// ---------------- host orchestration ----------------
extern "C" void kernel_launch(void* const* d_in, const int* in_sizes, int n_in,
                              void* d_out, int out_size) {
    const float* x = (const float*)d_in[0];
    const int* ei  = (const int*)d_in[1];
    const int E = in_sizes[1] / 2;
    const int N = in_sizes[0] / 128;
    const int* row = ei;
    const int* col = ei + E;

    float *dinv, *nrm, *h, *b0, *ag, *b2, *b3, *b4;
    int* deg;
    cudaGetSymbolAddress((void**)&dinv, g_dinv);
    cudaGetSymbolAddress((void**)&deg,  g_deg);
    cudaGetSymbolAddress((void**)&nrm,  g_norm);
    cudaGetSymbolAddress((void**)&h,    g_h);
    cudaGetSymbolAddress((void**)&b0,   g_buf0);
    cudaGetSymbolAddress((void**)&ag,   g_agg);
    cudaGetSymbolAddress((void**)&b2,   g_buf2);
    cudaGetSymbolAddress((void**)&b3,   g_buf3);
    cudaGetSymbolAddress((void**)&b4,   g_buf4);

    // gcn_norm
    k_zero_int<<<(N + 255) / 256, 256>>>(deg, N);
    k_deg<<<(E + 255) / 256, 256>>>(col, deg, E);
    k_dinv<<<(N + 255) / 256, 256>>>(deg, dinv, N);
    k_norm<<<(E + 255) / 256, 256>>>(row, col, dinv, nrm, E);

    static const int FI[6] = {128, 64, 64, 64, 64, 64};
    static const int FOv[6] = {64, 64, 64, 64, 64, 32};
    static const int Kv[6] = {2, 2, 2, 2, 2, 1};
    static const int Tv[6] = {2, 2, 2, 2, 2, 1};

    const float* cur = x;

    for (int L = 0; L < 6; L++) {
        const float* w  = (const float*)d_in[2 + L * 5 + 0];
        const float* iw = (const float*)d_in[2 + L * 5 + 1];
        const float* rw = (const float*)d_in[2 + L * 5 + 2];
        const float* dw = (const float*)d_in[2 + L * 5 + 3];
        const float* bb = (const float*)d_in[2 + L * 5 + 4];
        const int fi = FI[L], fo = FOv[L], K = Kv[L];
        const long sK = (long)N * fo;
        dim3 gg((N + 127) / 128, 1, K);
        const int nth = 32 * (fo / 8);

        auto gemm = [&](const float* A, const float* A2, long aK,
                        const float* B, long bK,
                        const float* D1, const float* D2, float al,
                        const float* bp, float* C, int Fin, int act) {
            if (fo == 64)
                k_gemm<64><<<gg, nth>>>(A, A2, aK, B, bK, D1, sK, D2, al, bp, C, sK, N, Fin, act);
            else
                k_gemm<32><<<gg, nth>>>(A, A2, aK, B, bK, D1, sK, D2, al, bp, C, sK, N, Fin, act);
        };

        // out0[k] = cur @ iw[k]
        gemm(cur, nullptr, 0, iw, (long)fi * fo, nullptr, nullptr, 0.f, nullptr, b0, fi, 0);

        // agg = prop(out0)
        const int F4 = fo / 4;
        const int chunks = K * F4;
        const int totz4 = (int)(K * sK / 4);
        k_zero4<<<(totz4 + 255) / 256, 256>>>((float4*)ag, totz4);
        {
            long nt = (long)E * chunks;
            k_scatter<<<(int)((nt + 255) / 256), 256>>>(b0, ag, row, col, nrm, E, F4, chunks, sK);
        }

        if (Tv[L] == 1) {
            // t=0: out = leaky(agg + cur@rw[0] + b[0]); K==1 -> sum is identity
            gemm(cur, nullptr, 0, rw, (long)fi * fo, ag, nullptr, 0.f, bb + 0, b2, fi, 1);
            // final: log_softmax
            k_logsoftmax<<<(N + 7) / 8, 256>>>(b2, (float*)d_out, N);
        } else {
            // t=0: out_t0 = leaky(agg + cur@rw[0,k] + b[0])
            gemm(cur, nullptr, 0, rw, (long)fi * fo, ag, nullptr, 0.f, bb + 0, b2, fi, 1);
            // t=1: t1 = out_t0 @ W[0,k]
            gemm(b2, nullptr, sK, w, (long)fo * fo, nullptr, nullptr, 0.f, nullptr, b3, fo, 0);
            // agg2 = prop(t1)
            k_zero4<<<(totz4 + 255) / 256, 256>>>((float4*)ag, totz4);
            {
                long nt = (long)E * chunks;
                k_scatter<<<(int)((nt + 255) / 256), 256>>>(b3, ag, row, col, nrm, E, F4, chunks, sK);
            }
            // dense1[k] = mean_k(out0) @ dw[1,k]   (mean fused into A-load)
            gemm(b0, b0 + sK, 0, dw + (long)K * fo * fo, (long)fo * fo,
                 nullptr, nullptr, 0.f, nullptr, b4, fo, 0);
            // final: tmp[k] = leaky(agg2 + cur@rw[1,k] + 0.6*dense1 + b[1])
            gemm(cur, nullptr, 0, rw + (long)K * fi * fo, (long)fi * fo,
                 ag, b4, 0.6f, bb + 1, b2, fi, 1);
            // y = relu(sum_k tmp) -> next layer input
            int n4 = (int)(sK / 4);
            k_combine<<<(n4 + 255) / 256, 256>>>((const float4*)b2, (const float4*)(b2 + sK),
                                                 (float4*)h, n4);
            cur = h;
        }
    }
    (void)n_in; (void)out_size;
}

// round 2
// speedup vs baseline: 1.9242x; 1.9242x over previous
#include <cuda_runtime.h>
#include <math.h>

#define NN 50000
#define EE 800000

// ---------------- scratch (static device globals; no allocations) ----------------
__device__ float g_dinv[NN];
__device__ int   g_deg[NN];          // degree, then reused as fill counter
__device__ int   g_rowptr[NN + 1];
__device__ int   g_bsum[256];
__device__ int   g_esrc[EE];         // CSR-by-destination: source node per slot
__device__ float g_ew[EE];           // edge weight (gcn norm) per slot
__device__ float g_h   [(size_t)NN * 64];       // inter-layer activations
__device__ float g_buf0[(size_t)2 * NN * 64];   // out0 (pre-propagate)
__device__ float g_agg [(size_t)2 * NN * 64];   // prop destination
__device__ float g_buf2[(size_t)2 * NN * 64];   // t0 output / final per-k
__device__ float g_buf3[(size_t)2 * NN * 64];   // out_t0 @ W
__device__ float g_buf4[(size_t)2 * NN * 64];   // dense1

// ---------------- setup kernels ----------------
__global__ void k_zero_int(int* p, int n) {
    int i = blockIdx.x * blockDim.x + threadIdx.x;
    if (i < n) p[i] = 0;
}

__global__ void k_deg(const int* __restrict__ col, int* __restrict__ deg, int E) {
    int e = blockIdx.x * blockDim.x + threadIdx.x;
    if (e < E) atomicAdd(&deg[col[e]], 1);
}

__global__ void k_dinv(const int* __restrict__ deg, float* __restrict__ dinv, int n) {
    int i = blockIdx.x * blockDim.x + threadIdx.x;
    if (i < n) {
        int d = deg[i];
        dinv[i] = (d > 0) ? rsqrtf((float)d) : 0.f;
    }
}

// block sums of deg (256 per block)
__global__ void k_blocksum(const int* __restrict__ deg, int* __restrict__ bsum, int n) {
    __shared__ int s[256];
    int i = blockIdx.x * 256 + threadIdx.x;
    s[threadIdx.x] = (i < n) ? deg[i] : 0;
    __syncthreads();
    for (int o = 128; o > 0; o >>= 1) {
        if (threadIdx.x < o) s[threadIdx.x] += s[threadIdx.x + o];
        __syncthreads();
    }
    if (threadIdx.x == 0) bsum[blockIdx.x] = s[0];
}

// single-block exclusive scan of block sums (nb <= 256)
__global__ void k_scanb(int* bsum, int nb) {
    __shared__ int s[256];
    int v = (threadIdx.x < nb) ? bsum[threadIdx.x] : 0;
    s[threadIdx.x] = v;
    __syncthreads();
    for (int o = 1; o < 256; o <<= 1) {
        int t = (threadIdx.x >= o) ? s[threadIdx.x - o] : 0;
        __syncthreads();
        s[threadIdx.x] += t;
        __syncthreads();
    }
    if (threadIdx.x < nb) bsum[threadIdx.x] = s[threadIdx.x] - v;  // exclusive
}

// per-element exclusive scan + block offset -> rowptr
__global__ void k_scanfinal(const int* __restrict__ deg, const int* __restrict__ bsum,
                            int* __restrict__ rowptr, int n, int E) {
    __shared__ int s[256];
    int i = blockIdx.x * 256 + threadIdx.x;
    int v = (i < n) ? deg[i] : 0;
    s[threadIdx.x] = v;
    __syncthreads();
    for (int o = 1; o < 256; o <<= 1) {
        int t = (threadIdx.x >= o) ? s[threadIdx.x - o] : 0;
        __syncthreads();
        s[threadIdx.x] += t;
        __syncthreads();
    }
    if (i < n) rowptr[i] = bsum[blockIdx.x] + s[threadIdx.x] - v;
    if (i == 0 && blockIdx.x == 0) rowptr[n] = E;
}

// scatter edges into CSR slots (one atomic per edge); ew = gcn norm
__global__ void k_fill(const int* __restrict__ row, const int* __restrict__ col,
                       const float* __restrict__ dinv,
                       const int* __restrict__ rowptr, int* __restrict__ counter,
                       int* __restrict__ esrc, float* __restrict__ ew, int E) {
    int e = blockIdx.x * blockDim.x + threadIdx.x;
    if (e >= E) return;
    int r = row[e], t = col[e];
    int p = rowptr[t] + atomicAdd(&counter[t], 1);
    esrc[p] = r;
    ew[p] = dinv[r] * dinv[t];
}

// ---------------- message passing: CSR gather (no atomics, no zeroing) ----------------
// thread = (node, chunk); chunk spans K * F/4 float4s. Lanes of the same node
// broadcast-read the edge list; gathers of the source row are coalesced.
template<int CH, int F4>
__global__ void k_prop(const float* __restrict__ src, float* __restrict__ dst,
                       const int* __restrict__ rowptr, const int* __restrict__ esrc,
                       const float* __restrict__ ew, int N, long sK) {
    int idx = blockIdx.x * blockDim.x + threadIdx.x;
    int n = idx / CH;
    if (n >= N) return;
    int c = idx - n * CH;
    int k = c / F4;
    int cc = c - k * F4;
    const float* sb = src + (long)k * sK + cc * 4;
    float4 acc = make_float4(0.f, 0.f, 0.f, 0.f);
    int s0 = rowptr[n], s1 = rowptr[n + 1];
#pragma unroll 4
    for (int j = s0; j < s1; j++) {
        int s = esrc[j];
        float wv = ew[j];
        float4 v = *(const float4*)(sb + (long)s * (F4 * 4));
        acc.x += v.x * wv; acc.y += v.y * wv;
        acc.z += v.z * wv; acc.w += v.w * wv;
    }
    *(float4*)(dst + (long)k * sK + ((long)n * F4 + cc) * 4) = acc;
}

// ---------------- fused SGEMM ----------------
// C[k] = act( A[k] @ B[k] + D1[k] + alpha2*D2[k] + bias_scalar )
// A2 != null: A-load becomes 0.5*(A+A2) (mean over K=2 fused).
template<int FO>
__global__ __launch_bounds__(32 * (FO / 8))
void k_gemm(const float* __restrict__ A, const float* __restrict__ A2, long aK,
            const float* __restrict__ B, long bK,
            const float* __restrict__ D1, long dK,
            const float* __restrict__ D2, float alpha2,
            const float* __restrict__ biasPtr,
            float* __restrict__ C, long cK,
            int nRows, int Fin, int act) {
    constexpr int TX = FO / 8;
    const int k = blockIdx.z;
    A += (long)k * aK;
    B += (long)k * bK;
    C += (long)k * cK;
    const float* d1 = D1 ? (D1 + (long)k * dK) : nullptr;
    const float* d2 = D2 ? (D2 + (long)k * dK) : nullptr;
    const float* a2 = A2 ? (A2 + (long)k * aK) : nullptr;

    __shared__ float Bs[128][FO];
    __shared__ float As[128][17];

    const int tid = threadIdx.x;
    const int nthreads = 32 * TX;
    const int tx = tid % TX;
    const int ty = tid / TX;
    const int row0 = blockIdx.x * 128;

    for (int i = tid; i < Fin * FO; i += nthreads)
        ((float*)Bs)[i] = B[i];

    float acc[4][8];
#pragma unroll
    for (int i = 0; i < 4; i++)
#pragma unroll
        for (int j = 0; j < 8; j++) acc[i][j] = 0.f;

    for (int kk0 = 0; kk0 < Fin; kk0 += 16) {
        __syncthreads();
        for (int i = tid; i < 128 * 16; i += nthreads) {
            int r = i >> 4, c = i & 15;
            int gr = row0 + r;
            float v = 0.f;
            if (gr < nRows) {
                v = A[(long)gr * Fin + kk0 + c];
                if (a2) v = 0.5f * (v + a2[(long)gr * Fin + kk0 + c]);
            }
            As[r][c] = v;
        }
        __syncthreads();
#pragma unroll
        for (int kk = 0; kk < 16; kk++) {
            float4 bA = *(const float4*)&Bs[kk0 + kk][tx * 8];
            float4 bB = *(const float4*)&Bs[kk0 + kk][tx * 8 + 4];
#pragma unroll
            for (int i = 0; i < 4; i++) {
                float a = As[ty * 4 + i][kk];
                acc[i][0] += a * bA.x; acc[i][1] += a * bA.y;
                acc[i][2] += a * bA.z; acc[i][3] += a * bA.w;
                acc[i][4] += a * bB.x; acc[i][5] += a * bB.y;
                acc[i][6] += a * bB.z; acc[i][7] += a * bB.w;
            }
        }
    }

    float bv = biasPtr ? __ldg(biasPtr) : 0.f;
#pragma unroll
    for (int i = 0; i < 4; i++) {
        int gr = row0 + ty * 4 + i;
        if (gr < nRows) {
            long base = (long)gr * FO + tx * 8;
#pragma unroll
            for (int j = 0; j < 8; j++) {
                float v = acc[i][j];
                if (d1) v += d1[base + j];
                if (d2) v += alpha2 * d2[base + j];
                v += bv;
                if (act) v = (v >= 0.f) ? v : 0.2f * v;
                C[base + j] = v;
            }
        }
    }
}

// y = relu(a + b) : sum over K=2 stacks + inter-layer ReLU
__global__ void k_combine(const float4* __restrict__ a, const float4* __restrict__ b,
                          float4* __restrict__ o, int n4) {
    int i = blockIdx.x * blockDim.x + threadIdx.x;
    if (i < n4) {
        float4 x = a[i], y = b[i];
        float4 r;
        r.x = fmaxf(x.x + y.x, 0.f);
        r.y = fmaxf(x.y + y.y, 0.f);
        r.z = fmaxf(x.z + y.z, 0.f);
        r.w = fmaxf(x.w + y.w, 0.f);
        o[i] = r;
    }
}

// warp-per-row log_softmax, C == 32 lanes
__global__ void k_logsoftmax(const float* __restrict__ in, float* __restrict__ out, int n) {
    int warp = (blockIdx.x * blockDim.x + threadIdx.x) >> 5;
    int lane = threadIdx.x & 31;
    if (warp >= n) return;
    float v = in[(long)warp * 32 + lane];
    float m = v;
#pragma unroll
    for (int o = 16; o > 0; o >>= 1) m = fmaxf(m, __shfl_xor_sync(0xffffffffu, m, o));
    float e = expf(v - m);
    float s = e;
#pragma unroll
    for (int o = 16; o > 0; o >>= 1) s += __shfl_xor_sync(0xffffffffu, s, o);
    out[(long)warp * 32 + lane] = v - m - logf(s);
}

// ---------------- host orchestration ----------------
extern "C" void kernel_launch(void* const* d_in, const int* in_sizes, int n_in,
                              void* d_out, int out_size) {
    const float* x = (const float*)d_in[0];
    const int* ei  = (const int*)d_in[1];
    const int E = in_sizes[1] / 2;
    const int N = in_sizes[0] / 128;
    const int* row = ei;
    const int* col = ei + E;

    float *dinv, *h, *b0, *ag, *b2, *b3, *b4, *ew;
    int *deg, *rowptr, *bsum, *esrc;
    cudaGetSymbolAddress((void**)&dinv,   g_dinv);
    cudaGetSymbolAddress((void**)&deg,    g_deg);
    cudaGetSymbolAddress((void**)&rowptr, g_rowptr);
    cudaGetSymbolAddress((void**)&bsum,   g_bsum);
    cudaGetSymbolAddress((void**)&esrc,   g_esrc);
    cudaGetSymbolAddress((void**)&ew,     g_ew);
    cudaGetSymbolAddress((void**)&h,      g_h);
    cudaGetSymbolAddress((void**)&b0,     g_buf0);
    cudaGetSymbolAddress((void**)&ag,     g_agg);
    cudaGetSymbolAddress((void**)&b2,     g_buf2);
    cudaGetSymbolAddress((void**)&b3,     g_buf3);
    cudaGetSymbolAddress((void**)&b4,     g_buf4);

    const int nb = (N + 255) / 256;

    // gcn_norm + CSR build (destination-sorted edge list)
    k_zero_int<<<nb, 256>>>(deg, N);
    k_deg<<<(E + 255) / 256, 256>>>(col, deg, E);
    k_dinv<<<nb, 256>>>(deg, dinv, N);
    k_blocksum<<<nb, 256>>>(deg, bsum, N);
    k_scanb<<<1, 256>>>(bsum, nb);
    k_scanfinal<<<nb, 256>>>(deg, bsum, rowptr, N, E);
    k_zero_int<<<nb, 256>>>(deg, N);   // reuse as fill counter
    k_fill<<<(E + 255) / 256, 256>>>(row, col, dinv, rowptr, deg, esrc, ew, E);

    static const int FI[6]  = {128, 64, 64, 64, 64, 64};
    static const int FOv[6] = {64, 64, 64, 64, 64, 32};
    static const int Kv[6]  = {2, 2, 2, 2, 2, 1};
    static const int Tv[6]  = {2, 2, 2, 2, 2, 1};

    const float* cur = x;

    for (int L = 0; L < 6; L++) {
        const float* w  = (const float*)d_in[2 + L * 5 + 0];
        const float* iw = (const float*)d_in[2 + L * 5 + 1];
        const float* rw = (const float*)d_in[2 + L * 5 + 2];
        const float* dw = (const float*)d_in[2 + L * 5 + 3];
        const float* bb = (const float*)d_in[2 + L * 5 + 4];
        const int fi = FI[L], fo = FOv[L], K = Kv[L];
        const long sK = (long)N * fo;
        dim3 gg((N + 127) / 128, 1, K);
        const int nth = 32 * (fo / 8);

        auto gemm = [&](const float* A, const float* A2, long aK,
                        const float* B, long bK,
                        const float* D1, const float* D2, float al,
                        const float* bp, float* C, int Fin, int act) {
            if (fo == 64)
                k_gemm<64><<<gg, nth>>>(A, A2, aK, B, bK, D1, sK, D2, al, bp, C, sK, N, Fin, act);
            else
                k_gemm<32><<<gg, nth>>>(A, A2, aK, B, bK, D1, sK, D2, al, bp, C, sK, N, Fin, act);
        };

        auto prop = [&](const float* src, float* dst) {
            if (fo == 64) {   // K=2, F4=16, CH=32
                long nt = (long)N * 32;
                k_prop<32, 16><<<(int)((nt + 255) / 256), 256>>>(src, dst, rowptr, esrc, ew, N, sK);
            } else {          // K=1, F4=8, CH=8
                long nt = (long)N * 8;
                k_prop<8, 8><<<(int)((nt + 255) / 256), 256>>>(src, dst, rowptr, esrc, ew, N, sK);
            }
        };

        // out0[k] = cur @ iw[k]
        gemm(cur, nullptr, 0, iw, (long)fi * fo, nullptr, nullptr, 0.f, nullptr, b0, fi, 0);
        // agg = prop(out0)
        prop(b0, ag);

        if (Tv[L] == 1) {
            // t=0: out = leaky(agg + cur@rw[0] + b[0]); K==1 -> sum over K is identity
            gemm(cur, nullptr, 0, rw, (long)fi * fo, ag, nullptr, 0.f, bb + 0, b2, fi, 1);
            k_logsoftmax<<<(N + 7) / 8, 256>>>(b2, (float*)d_out, N);
        } else {
            // t=0: out_t0 = leaky(agg + cur@rw[0,k] + b[0])
            gemm(cur, nullptr, 0, rw, (long)fi * fo, ag, nullptr, 0.f, bb + 0, b2, fi, 1);
            // t=1: t1 = out_t0 @ W[0,k]
            gemm(b2, nullptr, sK, w, (long)fo * fo, nullptr, nullptr, 0.f, nullptr, b3, fo, 0);
            // agg2 = prop(t1)
            prop(b3, ag);
            // dense1[k] = mean_k(out0) @ dw[1,k]   (mean fused into A-load)
            gemm(b0, b0 + sK, 0, dw + (long)K * fo * fo, (long)fo * fo,
                 nullptr, nullptr, 0.f, nullptr, b4, fo, 0);
            // final: tmp[k] = leaky(agg2 + cur@rw[1,k] + 0.6*dense1 + b[1])
            gemm(cur, nullptr, 0, rw + (long)K * fi * fo, (long)fi * fo,
                 ag, b4, 0.6f, bb + 1, b2, fi, 1);
            // y = relu(sum_k tmp) -> next layer input
            int n4 = (int)(sK / 4);
            k_combine<<<(n4 + 255) / 256, 256>>>((const float4*)b2, (const float4*)(b2 + sK),
                                                 (float4*)h, n4);
            cur = h;
        }
    }
    (void)n_in; (void)out_size;
}